// round 4
// baseline (speedup 1.0000x reference)
#include <cuda_runtime.h>
#include <math.h>

// Problem constants
#define B_   64
#define IN_  512
#define M_   1024
#define NG   6          // q,k,v,i,f,o
// gate scratch layout: [gate][b][m]
__device__ float g_gates[NG * B_ * M_];
__device__ float g_htilde[B_ * M_];

typedef unsigned long long u64;

// packed fp32x2 FMA: d = a*b + d (elementwise on the two lanes)
__device__ __forceinline__ void ffma2(u64& d, u64 a, u64 b) {
    asm("fma.rn.f32x2 %0, %1, %2, %0;" : "+l"(d) : "l"(a), "l"(b));
}

union U64F2 { u64 u; float2 f; };

// ---------------------------------------------------------------------------
// Kernel 1: fused 6-gate GEMM  out[g,b,n] = act_g( x[b,:] . W_g[n,:] + bias_g[n] )
// Tile BM=64 x BN=64 x BK=16, 256 threads, grid=96 (1 block/SM, all resident).
// FFMA2 (fp32x2) datapath: X stored DUPLICATED in smem so the row-pair operand
// of each packed FMA loads directly (no packing MOVs); W stored normally so
// a single LDS.128 yields two col-pairs. Inner loop per kk:
//   2x LDS.128 (X-dup) + 1x LDS.128 (W) + 8x FFMA2  == 16 scalar FMAs/thread.
// Double-buffered smem + register prefetch of the next global tile.
// ---------------------------------------------------------------------------
#define XDS 132   // X-dup row stride in floats (128 data + 4 pad, 16B-mult)
#define WST 68    // W row stride (64 data + 4 pad, 16B-mult)

__global__ __launch_bounds__(256)
void gates_gemm(const float* __restrict__ x,
                const float* __restrict__ Wq, const float* __restrict__ bq,
                const float* __restrict__ Wk, const float* __restrict__ bk,
                const float* __restrict__ Wv, const float* __restrict__ bv,
                const float* __restrict__ Wi, const float* __restrict__ bi,
                const float* __restrict__ Wf, const float* __restrict__ bf,
                const float* __restrict__ Wo, const float* __restrict__ bo)
{
    const int n_global0 = blockIdx.x * 64;          // [0, 6144)
    const int gate      = n_global0 >> 10;          // 0..5
    const int n_local0  = n_global0 & (M_ - 1);     // within-gate column base

    const float* W; const float* bias;
    switch (gate) {
        case 0: W = Wq; bias = bq; break;
        case 1: W = Wk; bias = bk; break;
        case 2: W = Wv; bias = bv; break;
        case 3: W = Wi; bias = bi; break;
        case 4: W = Wf; bias = bf; break;
        default: W = Wo; bias = bo; break;
    }

    __shared__ float Xd[2][16][XDS];   // [buf][k][2*b]  (duplicated pairs)
    __shared__ float Ws[2][16][WST];   // [buf][k][n]

    const int tid = threadIdx.x;
    const int tx = tid & 15;       // n direction: 16 groups x 4 cols
    const int ty = tid >> 4;       // b direction: 16 groups x 4 rows

    // global-load mapping: thread owns row lr, 4 consecutive k at lk
    const int lr = tid >> 2;         // 0..63
    const int lk = (tid & 3) * 4;    // 0,4,8,12

    const float* xg = x + lr * IN_ + lk;
    const float* wg = W + (n_local0 + lr) * IN_ + lk;

    float4 xr, wr;
    xr = *(const float4*)xg;
    wr = *(const float4*)wg;

    // acc[r][cp]: r = row within 4-row group, cp = col pair (lo=even col)
    u64 acc[4][2];
    #pragma unroll
    for (int r = 0; r < 4; r++) { acc[r][0] = 0ull; acc[r][1] = 0ull; }

    // store tile 0
    {
        *(float2*)&Xd[0][lk + 0][2 * lr] = make_float2(xr.x, xr.x);
        *(float2*)&Xd[0][lk + 1][2 * lr] = make_float2(xr.y, xr.y);
        *(float2*)&Xd[0][lk + 2][2 * lr] = make_float2(xr.z, xr.z);
        *(float2*)&Xd[0][lk + 3][2 * lr] = make_float2(xr.w, xr.w);
        Ws[0][lk + 0][lr] = wr.x;
        Ws[0][lk + 1][lr] = wr.y;
        Ws[0][lk + 2][lr] = wr.z;
        Ws[0][lk + 3][lr] = wr.w;
    }
    __syncthreads();

    int buf = 0;
    #pragma unroll 1
    for (int it = 0; it < IN_ / 16; it++) {
        // prefetch next global tile into registers (overlaps compute)
        if (it < IN_ / 16 - 1) {
            const int k0 = (it + 1) * 16;
            xr = *(const float4*)(xg + k0);
            wr = *(const float4*)(wg + k0);
        }

        #pragma unroll
        for (int kk = 0; kk < 16; kk++) {
            // X-dup: (a0,a0),(a1,a1) and (a2,a2),(a3,a3)
            ulonglong2 av0 = *(const ulonglong2*)&Xd[buf][kk][ty * 8];
            ulonglong2 av1 = *(const ulonglong2*)&Xd[buf][kk][ty * 8 + 4];
            // W: (w0,w1),(w2,w3)
            ulonglong2 wv  = *(const ulonglong2*)&Ws[buf][kk][tx * 4];
            ffma2(acc[0][0], av0.x, wv.x);
            ffma2(acc[0][1], av0.x, wv.y);
            ffma2(acc[1][0], av0.y, wv.x);
            ffma2(acc[1][1], av0.y, wv.y);
            ffma2(acc[2][0], av1.x, wv.x);
            ffma2(acc[2][1], av1.x, wv.y);
            ffma2(acc[3][0], av1.y, wv.x);
            ffma2(acc[3][1], av1.y, wv.y);
        }

        if (it < IN_ / 16 - 1) {
            const int nb = buf ^ 1;
            *(float2*)&Xd[nb][lk + 0][2 * lr] = make_float2(xr.x, xr.x);
            *(float2*)&Xd[nb][lk + 1][2 * lr] = make_float2(xr.y, xr.y);
            *(float2*)&Xd[nb][lk + 2][2 * lr] = make_float2(xr.z, xr.z);
            *(float2*)&Xd[nb][lk + 3][2 * lr] = make_float2(xr.w, xr.w);
            Ws[nb][lk + 0][lr] = wr.x;
            Ws[nb][lk + 1][lr] = wr.y;
            Ws[nb][lk + 2][lr] = wr.z;
            Ws[nb][lk + 3][lr] = wr.w;
            __syncthreads();
            buf = nb;
        }
    }

    // epilogue: bias + activation, vectorized write (float4 over n)
    float* out = g_gates + gate * (B_ * M_);
    const int n = n_local0 + tx * 4;
    const float4 bv4 = *(const float4*)&bias[n];
    #pragma unroll
    for (int r = 0; r < 4; r++) {
        const int b = ty * 4 + r;
        U64F2 p0, p1;
        p0.u = acc[r][0];
        p1.u = acc[r][1];
        float4 v;
        v.x = p0.f.x + bv4.x;
        v.y = p0.f.y + bv4.y;
        v.z = p1.f.x + bv4.z;
        v.w = p1.f.y + bv4.w;
        if (gate == 1) {
            v.x *= 0.03125f; v.y *= 0.03125f; v.z *= 0.03125f; v.w *= 0.03125f;
        } else if (gate == 3) {
            v.x = __expf(v.x); v.y = __expf(v.y); v.z = __expf(v.z); v.w = __expf(v.w);
        } else if (gate >= 4) {
            v.x = 1.f / (1.f + __expf(-v.x));
            v.y = 1.f / (1.f + __expf(-v.y));
            v.z = 1.f / (1.f + __expf(-v.z));
            v.w = 1.f / (1.f + __expf(-v.w));
        }
        *(float4*)&out[b * M_ + n] = v;
    }
}

// ---------------------------------------------------------------------------
// Kernel 2: C_t[b,m,:] = f[b,m]*C_prev[b,m,:] + (i*v)[b,m]*k[b,:]
//           h_tilde[b,m] = C_t[b,m,:] . q[b,:]     (fused, warp-reduced)
// grid = (16, 64): blockIdx.y = batch, blockIdx.x = 64-row chunk.
// 8 warps, warp owns row (chunk*64 + r*8 + warp) for r=0..7.
// Software-pipelined across rows: row r+1's 8 streaming loads are issued
// before row r's compute/store/reduce, keeping HBM saturated.
// ---------------------------------------------------------------------------
__global__ __launch_bounds__(256)
void update_C(const float* __restrict__ Cprev, float* __restrict__ Cout)
{
    const int b = blockIdx.y;
    __shared__ float sk[M_];
    __shared__ float sq[M_];

    const float* gq = g_gates + 0 * (B_ * M_) + b * M_;
    const float* gk = g_gates + 1 * (B_ * M_) + b * M_;
    ((float4*)sk)[threadIdx.x] = ((const float4*)gk)[threadIdx.x];
    ((float4*)sq)[threadIdx.x] = ((const float4*)gq)[threadIdx.x];
    __syncthreads();

    const int warp = threadIdx.x >> 5;
    const int lane = threadIdx.x & 31;
    const float* gv = g_gates + 2 * (B_ * M_) + b * M_;
    const float* gi = g_gates + 3 * (B_ * M_) + b * M_;
    const float* gf = g_gates + 4 * (B_ * M_) + b * M_;

    const float4* sk4 = (const float4*)sk;
    const float4* sq4 = (const float4*)sq;

    const int m_base = blockIdx.x * 64 + warp;    // rows m_base + 8*r

    // prologue: row 0 loads + scalars
    float4 cur[8], nxt[8];
    int m = m_base;
    float fm = gf[m];
    float cm = gi[m] * gv[m];
    {
        const float4* cp = (const float4*)(Cprev + ((size_t)b * M_ + m) * M_);
        #pragma unroll
        for (int j = 0; j < 8; j++) cur[j] = __ldcs(cp + j * 32 + lane);
    }

    #pragma unroll
    for (int r = 0; r < 8; r++) {
        float fmn = 0.f, cmn = 0.f;
        if (r < 7) {
            const int mn = m_base + (r + 1) * 8;
            fmn = gf[mn];
            cmn = gi[mn] * gv[mn];
            const float4* cpn = (const float4*)(Cprev + ((size_t)b * M_ + mn) * M_);
            #pragma unroll
            for (int j = 0; j < 8; j++) nxt[j] = __ldcs(cpn + j * 32 + lane);
        }

        float4* co = (float4*)(Cout + ((size_t)b * M_ + m) * M_);
        float dot0 = 0.f, dot1 = 0.f;
        #pragma unroll
        for (int j = 0; j < 8; j++) {
            const int n4 = j * 32 + lane;
            float4 kk = sk4[n4];
            float4 qq = sq4[n4];
            float4 o;
            o.x = fmaf(fm, cur[j].x, cm * kk.x);
            o.y = fmaf(fm, cur[j].y, cm * kk.y);
            o.z = fmaf(fm, cur[j].z, cm * kk.z);
            o.w = fmaf(fm, cur[j].w, cm * kk.w);
            __stcs(co + n4, o);
            if (j & 1) {
                dot1 = fmaf(o.x, qq.x, dot1);
                dot1 = fmaf(o.y, qq.y, dot1);
                dot1 = fmaf(o.z, qq.z, dot1);
                dot1 = fmaf(o.w, qq.w, dot1);
            } else {
                dot0 = fmaf(o.x, qq.x, dot0);
                dot0 = fmaf(o.y, qq.y, dot0);
                dot0 = fmaf(o.z, qq.z, dot0);
                dot0 = fmaf(o.w, qq.w, dot0);
            }
        }
        float dot = dot0 + dot1;
        #pragma unroll
        for (int off = 16; off; off >>= 1)
            dot += __shfl_xor_sync(0xffffffffu, dot, off);
        if (lane == 0) g_htilde[b * M_ + m] = dot;

        // rotate pipeline
        m = m_base + (r + 1) * 8;
        fm = fmn;
        cm = cmn;
        #pragma unroll
        for (int j = 0; j < 8; j++) cur[j] = nxt[j];
    }
}

// ---------------------------------------------------------------------------
// Kernel 3: n_t = f*n_prev + i*k ; denom = max(n_t.q, 1) ; h_t = o*h_tilde/denom
// ---------------------------------------------------------------------------
__global__ __launch_bounds__(256)
void finalize(const float* __restrict__ nprev,
              float* __restrict__ out_h, float* __restrict__ out_n)
{
    const int b   = blockIdx.x;
    const int tid = threadIdx.x;

    const float* gq = g_gates + 0 * (B_ * M_) + b * M_;
    const float* gk = g_gates + 1 * (B_ * M_) + b * M_;
    const float* gi = g_gates + 3 * (B_ * M_) + b * M_;
    const float* gf = g_gates + 4 * (B_ * M_) + b * M_;
    const float* go = g_gates + 5 * (B_ * M_) + b * M_;

    float part = 0.f;
    #pragma unroll
    for (int r = 0; r < 4; r++) {
        int j = tid + r * 256;
        float n = fmaf(gf[j], nprev[b * M_ + j], gi[j] * gk[j]);
        out_n[b * M_ + j] = n;
        part = fmaf(n, gq[j], part);
    }

    __shared__ float red[256];
    red[tid] = part;
    __syncthreads();
    #pragma unroll
    for (int s = 128; s > 0; s >>= 1) {
        if (tid < s) red[tid] += red[tid + s];
        __syncthreads();
    }
    const float denom = fmaxf(red[0], 1.0f);
    const float inv   = 1.0f / denom;

    #pragma unroll
    for (int r = 0; r < 4; r++) {
        int j = tid + r * 256;
        out_h[b * M_ + j] = go[j] * g_htilde[b * M_ + j] * inv;
    }
}

// ---------------------------------------------------------------------------
// Launch. Inputs (metadata order):
// 0 x, 1 h_prev, 2 c_prev, 3 C_prev, 4 n_prev, 5 m_prev,
// 6 Wq, 7 bq, 8 Wk, 9 bk, 10 Wv, 11 bv, 12 Wi, 13 bi, 14 Wf, 15 bf, 16 Wo, 17 bo
// Output: concat(h_t [64*1024], C_t [64*1024*1024], n_t [64*1024])
// ---------------------------------------------------------------------------
extern "C" void kernel_launch(void* const* d_in, const int* in_sizes, int n_in,
                              void* d_out, int out_size)
{
    const float* x     = (const float*)d_in[0];
    const float* Cprev = (const float*)d_in[3];
    const float* nprev = (const float*)d_in[4];

    const float* Wq = (const float*)d_in[6];  const float* bq = (const float*)d_in[7];
    const float* Wk = (const float*)d_in[8];  const float* bk = (const float*)d_in[9];
    const float* Wv = (const float*)d_in[10]; const float* bv = (const float*)d_in[11];
    const float* Wi = (const float*)d_in[12]; const float* bi = (const float*)d_in[13];
    const float* Wf = (const float*)d_in[14]; const float* bf = (const float*)d_in[15];
    const float* Wo = (const float*)d_in[16]; const float* bo = (const float*)d_in[17];

    float* out   = (float*)d_out;
    float* out_h = out;                                    // [64*1024]
    float* out_C = out + (size_t)B_ * M_;                  // [64*1024*1024]
    float* out_n = out + (size_t)B_ * M_ + (size_t)B_ * M_ * M_;

    gates_gemm<<<96, 256>>>(x, Wq, bq, Wk, bk, Wv, bv, Wi, bi, Wf, bf, Wo, bo);

    dim3 grid2(16, 64);
    update_C<<<grid2, 256>>>(Cprev, out_C);

    finalize<<<B_, 256>>>(nprev, out_h, out_n);
}

// round 5
// speedup vs baseline: 1.0748x; 1.0748x over previous
#include <cuda_runtime.h>
#include <math.h>

// Problem constants
#define B_   64
#define IN_  512
#define M_   1024
#define NG   6          // q,k,v,i,f,o
#define NSPLIT 4        // split-K factor
#define KSL  (IN_ / NSPLIT)   // 128 per split

// scratch
__device__ float g_gates[NG * B_ * M_];          // [gate][b][m]
__device__ float g_htilde[B_ * M_];
__device__ float g_part[NSPLIT * B_ * NG * M_];  // [s][b][n_global]  n_global in [0,6144)

// ---------------------------------------------------------------------------
// Kernel 1a: split-K fused 6-gate GEMM partials.
// grid = (96, 4): bx -> 64-wide column tile over the 6144 gate-columns,
//                 by -> K split (128 wide). 256 threads, 4x4 microtile,
// double-buffered smem (BK=32) with register prefetch.
// partial[s][b][n_global] = sum_{k in slice s} x[b,k] * W[n,k]
// ---------------------------------------------------------------------------
#define SST 68

__global__ __launch_bounds__(256)
void gates_gemm_sk(const float* __restrict__ x,
                   const float* __restrict__ Wq, const float* __restrict__ Wk,
                   const float* __restrict__ Wv, const float* __restrict__ Wi,
                   const float* __restrict__ Wf, const float* __restrict__ Wo)
{
    const int n_global0 = blockIdx.x * 64;          // [0, 6144)
    const int gate      = n_global0 >> 10;          // 0..5
    const int n_local0  = n_global0 & (M_ - 1);
    const int s         = blockIdx.y;               // K split index
    const int k_base    = s * KSL;

    const float* W;
    switch (gate) {
        case 0: W = Wq; break;
        case 1: W = Wk; break;
        case 2: W = Wv; break;
        case 3: W = Wi; break;
        case 4: W = Wf; break;
        default: W = Wo; break;
    }

    __shared__ float Xs[2][32][SST];   // [buf][k][b]
    __shared__ float Ws[2][32][SST];   // [buf][k][n]

    const int tid = threadIdx.x;
    const int tx = tid & 15;       // n: 16 groups x 4
    const int ty = tid >> 4;       // b: 16 groups x 4

    const int lr = tid >> 2;         // 0..63
    const int lk = (tid & 3) * 8;    // 0,8,16,24

    const float* xg = x + lr * IN_ + k_base + lk;
    const float* wg = W + (n_local0 + lr) * IN_ + k_base + lk;

    float4 xr0, xr1, wr0, wr1;
    xr0 = *(const float4*)(xg + 0);
    xr1 = *(const float4*)(xg + 4);
    wr0 = *(const float4*)(wg + 0);
    wr1 = *(const float4*)(wg + 4);

    float acc[4][4];
    #pragma unroll
    for (int r = 0; r < 4; r++)
        #pragma unroll
        for (int c = 0; c < 4; c++) acc[r][c] = 0.f;

    int buf = 0;
    {
        Xs[0][lk + 0][lr] = xr0.x; Xs[0][lk + 1][lr] = xr0.y;
        Xs[0][lk + 2][lr] = xr0.z; Xs[0][lk + 3][lr] = xr0.w;
        Xs[0][lk + 4][lr] = xr1.x; Xs[0][lk + 5][lr] = xr1.y;
        Xs[0][lk + 6][lr] = xr1.z; Xs[0][lk + 7][lr] = xr1.w;
        Ws[0][lk + 0][lr] = wr0.x; Ws[0][lk + 1][lr] = wr0.y;
        Ws[0][lk + 2][lr] = wr0.z; Ws[0][lk + 3][lr] = wr0.w;
        Ws[0][lk + 4][lr] = wr1.x; Ws[0][lk + 5][lr] = wr1.y;
        Ws[0][lk + 6][lr] = wr1.z; Ws[0][lk + 7][lr] = wr1.w;
    }
    __syncthreads();

    #pragma unroll 1
    for (int it = 0; it < KSL / 32; it++) {
        if (it < KSL / 32 - 1) {
            const int k0 = (it + 1) * 32;
            xr0 = *(const float4*)(xg + k0 + 0);
            xr1 = *(const float4*)(xg + k0 + 4);
            wr0 = *(const float4*)(wg + k0 + 0);
            wr1 = *(const float4*)(wg + k0 + 4);
        }

        #pragma unroll
        for (int kk = 0; kk < 32; kk++) {
            float4 a  = *(const float4*)&Xs[buf][kk][ty * 4];
            float4 bb = *(const float4*)&Ws[buf][kk][tx * 4];
            acc[0][0] = fmaf(a.x, bb.x, acc[0][0]);
            acc[0][1] = fmaf(a.x, bb.y, acc[0][1]);
            acc[0][2] = fmaf(a.x, bb.z, acc[0][2]);
            acc[0][3] = fmaf(a.x, bb.w, acc[0][3]);
            acc[1][0] = fmaf(a.y, bb.x, acc[1][0]);
            acc[1][1] = fmaf(a.y, bb.y, acc[1][1]);
            acc[1][2] = fmaf(a.y, bb.z, acc[1][2]);
            acc[1][3] = fmaf(a.y, bb.w, acc[1][3]);
            acc[2][0] = fmaf(a.z, bb.x, acc[2][0]);
            acc[2][1] = fmaf(a.z, bb.y, acc[2][1]);
            acc[2][2] = fmaf(a.z, bb.z, acc[2][2]);
            acc[2][3] = fmaf(a.z, bb.w, acc[2][3]);
            acc[3][0] = fmaf(a.w, bb.x, acc[3][0]);
            acc[3][1] = fmaf(a.w, bb.y, acc[3][1]);
            acc[3][2] = fmaf(a.w, bb.z, acc[3][2]);
            acc[3][3] = fmaf(a.w, bb.w, acc[3][3]);
        }

        if (it < KSL / 32 - 1) {
            const int nb = buf ^ 1;
            Xs[nb][lk + 0][lr] = xr0.x; Xs[nb][lk + 1][lr] = xr0.y;
            Xs[nb][lk + 2][lr] = xr0.z; Xs[nb][lk + 3][lr] = xr0.w;
            Xs[nb][lk + 4][lr] = xr1.x; Xs[nb][lk + 5][lr] = xr1.y;
            Xs[nb][lk + 6][lr] = xr1.z; Xs[nb][lk + 7][lr] = xr1.w;
            Ws[nb][lk + 0][lr] = wr0.x; Ws[nb][lk + 1][lr] = wr0.y;
            Ws[nb][lk + 2][lr] = wr0.z; Ws[nb][lk + 3][lr] = wr0.w;
            Ws[nb][lk + 4][lr] = wr1.x; Ws[nb][lk + 5][lr] = wr1.y;
            Ws[nb][lk + 6][lr] = wr1.z; Ws[nb][lk + 7][lr] = wr1.w;
            __syncthreads();
            buf = nb;
        }
    }

    // write partials: [s][b][n_global], float4 over n (stays in L2)
    const int n = n_global0 + tx * 4;
    #pragma unroll
    for (int r = 0; r < 4; r++) {
        const int b = ty * 4 + r;
        float4 v = make_float4(acc[r][0], acc[r][1], acc[r][2], acc[r][3]);
        *(float4*)&g_part[((size_t)s * B_ + b) * (NG * M_) + n] = v;
    }
}

// ---------------------------------------------------------------------------
// Kernel 1b: reduce partials + bias + activation -> g_gates[gate][b][m]
// one thread per float4 column chunk: 64*6144/4 = 98304 threads = 384 blocks.
// ---------------------------------------------------------------------------
__global__ __launch_bounds__(256)
void gates_reduce(const float* __restrict__ bq, const float* __restrict__ bk,
                  const float* __restrict__ bv, const float* __restrict__ bi,
                  const float* __restrict__ bf, const float* __restrict__ bo)
{
    const int idx = blockIdx.x * 256 + threadIdx.x;   // [0, 98304)
    const int b   = idx / (NG * M_ / 4);
    const int c4  = idx % (NG * M_ / 4);
    const int n   = c4 * 4;                            // global gate-col [0,6144)
    const int gate = n >> 10;
    const int nl   = n & (M_ - 1);

    const float* bias;
    switch (gate) {
        case 0: bias = bq; break;
        case 1: bias = bk; break;
        case 2: bias = bv; break;
        case 3: bias = bi; break;
        case 4: bias = bf; break;
        default: bias = bo; break;
    }

    float4 acc = *(const float4*)&g_part[((size_t)0 * B_ + b) * (NG * M_) + n];
    #pragma unroll
    for (int s = 1; s < NSPLIT; s++) {
        float4 p = *(const float4*)&g_part[((size_t)s * B_ + b) * (NG * M_) + n];
        acc.x += p.x; acc.y += p.y; acc.z += p.z; acc.w += p.w;
    }
    const float4 bv4 = *(const float4*)&bias[nl];
    acc.x += bv4.x; acc.y += bv4.y; acc.z += bv4.z; acc.w += bv4.w;

    if (gate == 1) {
        acc.x *= 0.03125f; acc.y *= 0.03125f; acc.z *= 0.03125f; acc.w *= 0.03125f;
    } else if (gate == 3) {
        acc.x = __expf(acc.x); acc.y = __expf(acc.y);
        acc.z = __expf(acc.z); acc.w = __expf(acc.w);
    } else if (gate >= 4) {
        acc.x = 1.f / (1.f + __expf(-acc.x));
        acc.y = 1.f / (1.f + __expf(-acc.y));
        acc.z = 1.f / (1.f + __expf(-acc.z));
        acc.w = 1.f / (1.f + __expf(-acc.w));
    }
    *(float4*)&g_gates[(size_t)gate * (B_ * M_) + b * M_ + nl] = acc;
}

// ---------------------------------------------------------------------------
// Kernel 2: C_t[b,m,:] = f[b,m]*C_prev[b,m,:] + (i*v)[b,m]*k[b,:]
//           h_tilde[b,m] = C_t[b,m,:] . q[b,:]     (fused, warp-reduced)
// Software-pipelined across rows (R4 version — measured ~3us better than R3).
// ---------------------------------------------------------------------------
__global__ __launch_bounds__(256)
void update_C(const float* __restrict__ Cprev, float* __restrict__ Cout)
{
    const int b = blockIdx.y;
    __shared__ float sk[M_];
    __shared__ float sq[M_];

    const float* gq = g_gates + 0 * (B_ * M_) + b * M_;
    const float* gk = g_gates + 1 * (B_ * M_) + b * M_;
    ((float4*)sk)[threadIdx.x] = ((const float4*)gk)[threadIdx.x];
    ((float4*)sq)[threadIdx.x] = ((const float4*)gq)[threadIdx.x];
    __syncthreads();

    const int warp = threadIdx.x >> 5;
    const int lane = threadIdx.x & 31;
    const float* gv = g_gates + 2 * (B_ * M_) + b * M_;
    const float* gi = g_gates + 3 * (B_ * M_) + b * M_;
    const float* gf = g_gates + 4 * (B_ * M_) + b * M_;

    const float4* sk4 = (const float4*)sk;
    const float4* sq4 = (const float4*)sq;

    const int m_base = blockIdx.x * 64 + warp;

    float4 cur[8], nxt[8];
    int m = m_base;
    float fm = gf[m];
    float cm = gi[m] * gv[m];
    {
        const float4* cp = (const float4*)(Cprev + ((size_t)b * M_ + m) * M_);
        #pragma unroll
        for (int j = 0; j < 8; j++) cur[j] = __ldcs(cp + j * 32 + lane);
    }

    #pragma unroll
    for (int r = 0; r < 8; r++) {
        float fmn = 0.f, cmn = 0.f;
        if (r < 7) {
            const int mn = m_base + (r + 1) * 8;
            fmn = gf[mn];
            cmn = gi[mn] * gv[mn];
            const float4* cpn = (const float4*)(Cprev + ((size_t)b * M_ + mn) * M_);
            #pragma unroll
            for (int j = 0; j < 8; j++) nxt[j] = __ldcs(cpn + j * 32 + lane);
        }

        float4* co = (float4*)(Cout + ((size_t)b * M_ + m) * M_);
        float dot0 = 0.f, dot1 = 0.f;
        #pragma unroll
        for (int j = 0; j < 8; j++) {
            const int n4 = j * 32 + lane;
            float4 kk = sk4[n4];
            float4 qq = sq4[n4];
            float4 o;
            o.x = fmaf(fm, cur[j].x, cm * kk.x);
            o.y = fmaf(fm, cur[j].y, cm * kk.y);
            o.z = fmaf(fm, cur[j].z, cm * kk.z);
            o.w = fmaf(fm, cur[j].w, cm * kk.w);
            __stcs(co + n4, o);
            if (j & 1) {
                dot1 = fmaf(o.x, qq.x, dot1);
                dot1 = fmaf(o.y, qq.y, dot1);
                dot1 = fmaf(o.z, qq.z, dot1);
                dot1 = fmaf(o.w, qq.w, dot1);
            } else {
                dot0 = fmaf(o.x, qq.x, dot0);
                dot0 = fmaf(o.y, qq.y, dot0);
                dot0 = fmaf(o.z, qq.z, dot0);
                dot0 = fmaf(o.w, qq.w, dot0);
            }
        }
        float dot = dot0 + dot1;
        #pragma unroll
        for (int off = 16; off; off >>= 1)
            dot += __shfl_xor_sync(0xffffffffu, dot, off);
        if (lane == 0) g_htilde[b * M_ + m] = dot;

        m = m_base + (r + 1) * 8;
        fm = fmn;
        cm = cmn;
        #pragma unroll
        for (int j = 0; j < 8; j++) cur[j] = nxt[j];
    }
}

// ---------------------------------------------------------------------------
// Kernel 3: n_t = f*n_prev + i*k ; denom = max(n_t.q, 1) ; h_t = o*h_tilde/denom
// ---------------------------------------------------------------------------
__global__ __launch_bounds__(256)
void finalize(const float* __restrict__ nprev,
              float* __restrict__ out_h, float* __restrict__ out_n)
{
    const int b   = blockIdx.x;
    const int tid = threadIdx.x;

    const float* gq = g_gates + 0 * (B_ * M_) + b * M_;
    const float* gk = g_gates + 1 * (B_ * M_) + b * M_;
    const float* gi = g_gates + 3 * (B_ * M_) + b * M_;
    const float* gf = g_gates + 4 * (B_ * M_) + b * M_;
    const float* go = g_gates + 5 * (B_ * M_) + b * M_;

    float part = 0.f;
    #pragma unroll
    for (int r = 0; r < 4; r++) {
        int j = tid + r * 256;
        float n = fmaf(gf[j], nprev[b * M_ + j], gi[j] * gk[j]);
        out_n[b * M_ + j] = n;
        part = fmaf(n, gq[j], part);
    }

    __shared__ float red[256];
    red[tid] = part;
    __syncthreads();
    #pragma unroll
    for (int s = 128; s > 0; s >>= 1) {
        if (tid < s) red[tid] += red[tid + s];
        __syncthreads();
    }
    const float denom = fmaxf(red[0], 1.0f);
    const float inv   = 1.0f / denom;

    #pragma unroll
    for (int r = 0; r < 4; r++) {
        int j = tid + r * 256;
        out_h[b * M_ + j] = go[j] * g_htilde[b * M_ + j] * inv;
    }
}

// ---------------------------------------------------------------------------
// Launch. Inputs (metadata order):
// 0 x, 1 h_prev, 2 c_prev, 3 C_prev, 4 n_prev, 5 m_prev,
// 6 Wq, 7 bq, 8 Wk, 9 bk, 10 Wv, 11 bv, 12 Wi, 13 bi, 14 Wf, 15 bf, 16 Wo, 17 bo
// Output: concat(h_t [64*1024], C_t [64*1024*1024], n_t [64*1024])
// ---------------------------------------------------------------------------
extern "C" void kernel_launch(void* const* d_in, const int* in_sizes, int n_in,
                              void* d_out, int out_size)
{
    const float* x     = (const float*)d_in[0];
    const float* Cprev = (const float*)d_in[3];
    const float* nprev = (const float*)d_in[4];

    const float* Wq = (const float*)d_in[6];  const float* bq = (const float*)d_in[7];
    const float* Wk = (const float*)d_in[8];  const float* bk = (const float*)d_in[9];
    const float* Wv = (const float*)d_in[10]; const float* bv = (const float*)d_in[11];
    const float* Wi = (const float*)d_in[12]; const float* bi = (const float*)d_in[13];
    const float* Wf = (const float*)d_in[14]; const float* bf = (const float*)d_in[15];
    const float* Wo = (const float*)d_in[16]; const float* bo = (const float*)d_in[17];

    float* out   = (float*)d_out;
    float* out_h = out;                                    // [64*1024]
    float* out_C = out + (size_t)B_ * M_;                  // [64*1024*1024]
    float* out_n = out + (size_t)B_ * M_ + (size_t)B_ * M_ * M_;

    dim3 grid1(96, NSPLIT);
    gates_gemm_sk<<<grid1, 256>>>(x, Wq, Wk, Wv, Wi, Wf, Wo);

    gates_reduce<<<384, 256>>>(bq, bk, bv, bi, bf, bo);

    dim3 grid2(16, 64);
    update_C<<<grid2, 256>>>(Cprev, out_C);

    finalize<<<B_, 256>>>(nprev, out_h, out_n);
}

// round 6
// speedup vs baseline: 1.1101x; 1.0329x over previous
#include <cuda_runtime.h>
#include <math.h>

// Problem constants
#define B_   64
#define IN_  512
#define M_   1024
#define NG   6          // q,k,v,i,f,o
#define NSPLIT 4        // split-K factor
#define KSL  (IN_ / NSPLIT)   // 128 per split

// scratch
__device__ float g_gates[NG * B_ * M_];          // [gate][b][m]
__device__ float g_part[NSPLIT * B_ * NG * M_];  // [s][b][n_global]

// ---------------------------------------------------------------------------
// Kernel 1a: split-K fused 6-gate GEMM partials.
// grid = (96, 4). 256 threads, 4x4 microtile, double-buffered smem (BK=32).
// ---------------------------------------------------------------------------
#define SST 68

__global__ __launch_bounds__(256)
void gates_gemm_sk(const float* __restrict__ x,
                   const float* __restrict__ Wq, const float* __restrict__ Wk,
                   const float* __restrict__ Wv, const float* __restrict__ Wi,
                   const float* __restrict__ Wf, const float* __restrict__ Wo)
{
    const int n_global0 = blockIdx.x * 64;
    const int gate      = n_global0 >> 10;
    const int n_local0  = n_global0 & (M_ - 1);
    const int s         = blockIdx.y;
    const int k_base    = s * KSL;

    const float* W;
    switch (gate) {
        case 0: W = Wq; break;
        case 1: W = Wk; break;
        case 2: W = Wv; break;
        case 3: W = Wi; break;
        case 4: W = Wf; break;
        default: W = Wo; break;
    }

    __shared__ float Xs[2][32][SST];
    __shared__ float Ws[2][32][SST];

    const int tid = threadIdx.x;
    const int tx = tid & 15;
    const int ty = tid >> 4;

    const int lr = tid >> 2;
    const int lk = (tid & 3) * 8;

    const float* xg = x + lr * IN_ + k_base + lk;
    const float* wg = W + (n_local0 + lr) * IN_ + k_base + lk;

    float4 xr0, xr1, wr0, wr1;
    xr0 = *(const float4*)(xg + 0);
    xr1 = *(const float4*)(xg + 4);
    wr0 = *(const float4*)(wg + 0);
    wr1 = *(const float4*)(wg + 4);

    float acc[4][4];
    #pragma unroll
    for (int r = 0; r < 4; r++)
        #pragma unroll
        for (int c = 0; c < 4; c++) acc[r][c] = 0.f;

    int buf = 0;
    {
        Xs[0][lk + 0][lr] = xr0.x; Xs[0][lk + 1][lr] = xr0.y;
        Xs[0][lk + 2][lr] = xr0.z; Xs[0][lk + 3][lr] = xr0.w;
        Xs[0][lk + 4][lr] = xr1.x; Xs[0][lk + 5][lr] = xr1.y;
        Xs[0][lk + 6][lr] = xr1.z; Xs[0][lk + 7][lr] = xr1.w;
        Ws[0][lk + 0][lr] = wr0.x; Ws[0][lk + 1][lr] = wr0.y;
        Ws[0][lk + 2][lr] = wr0.z; Ws[0][lk + 3][lr] = wr0.w;
        Ws[0][lk + 4][lr] = wr1.x; Ws[0][lk + 5][lr] = wr1.y;
        Ws[0][lk + 6][lr] = wr1.z; Ws[0][lk + 7][lr] = wr1.w;
    }
    __syncthreads();

    #pragma unroll 1
    for (int it = 0; it < KSL / 32; it++) {
        if (it < KSL / 32 - 1) {
            const int k0 = (it + 1) * 32;
            xr0 = *(const float4*)(xg + k0 + 0);
            xr1 = *(const float4*)(xg + k0 + 4);
            wr0 = *(const float4*)(wg + k0 + 0);
            wr1 = *(const float4*)(wg + k0 + 4);
        }

        #pragma unroll
        for (int kk = 0; kk < 32; kk++) {
            float4 a  = *(const float4*)&Xs[buf][kk][ty * 4];
            float4 bb = *(const float4*)&Ws[buf][kk][tx * 4];
            acc[0][0] = fmaf(a.x, bb.x, acc[0][0]);
            acc[0][1] = fmaf(a.x, bb.y, acc[0][1]);
            acc[0][2] = fmaf(a.x, bb.z, acc[0][2]);
            acc[0][3] = fmaf(a.x, bb.w, acc[0][3]);
            acc[1][0] = fmaf(a.y, bb.x, acc[1][0]);
            acc[1][1] = fmaf(a.y, bb.y, acc[1][1]);
            acc[1][2] = fmaf(a.y, bb.z, acc[1][2]);
            acc[1][3] = fmaf(a.y, bb.w, acc[1][3]);
            acc[2][0] = fmaf(a.z, bb.x, acc[2][0]);
            acc[2][1] = fmaf(a.z, bb.y, acc[2][1]);
            acc[2][2] = fmaf(a.z, bb.z, acc[2][2]);
            acc[2][3] = fmaf(a.z, bb.w, acc[2][3]);
            acc[3][0] = fmaf(a.w, bb.x, acc[3][0]);
            acc[3][1] = fmaf(a.w, bb.y, acc[3][1]);
            acc[3][2] = fmaf(a.w, bb.z, acc[3][2]);
            acc[3][3] = fmaf(a.w, bb.w, acc[3][3]);
        }

        if (it < KSL / 32 - 1) {
            const int nb = buf ^ 1;
            Xs[nb][lk + 0][lr] = xr0.x; Xs[nb][lk + 1][lr] = xr0.y;
            Xs[nb][lk + 2][lr] = xr0.z; Xs[nb][lk + 3][lr] = xr0.w;
            Xs[nb][lk + 4][lr] = xr1.x; Xs[nb][lk + 5][lr] = xr1.y;
            Xs[nb][lk + 6][lr] = xr1.z; Xs[nb][lk + 7][lr] = xr1.w;
            Ws[nb][lk + 0][lr] = wr0.x; Ws[nb][lk + 1][lr] = wr0.y;
            Ws[nb][lk + 2][lr] = wr0.z; Ws[nb][lk + 3][lr] = wr0.w;
            Ws[nb][lk + 4][lr] = wr1.x; Ws[nb][lk + 5][lr] = wr1.y;
            Ws[nb][lk + 6][lr] = wr1.z; Ws[nb][lk + 7][lr] = wr1.w;
            __syncthreads();
            buf = nb;
        }
    }

    const int n = n_global0 + tx * 4;
    #pragma unroll
    for (int r = 0; r < 4; r++) {
        const int b = ty * 4 + r;
        float4 v = make_float4(acc[r][0], acc[r][1], acc[r][2], acc[r][3]);
        *(float4*)&g_part[((size_t)s * B_ + b) * (NG * M_) + n] = v;
    }
}

// ---------------------------------------------------------------------------
// Kernel 1b: reduce partials + bias + activation -> g_gates[gate][b][m]
// ---------------------------------------------------------------------------
__global__ __launch_bounds__(256)
void gates_reduce(const float* __restrict__ bq, const float* __restrict__ bk,
                  const float* __restrict__ bv, const float* __restrict__ bi,
                  const float* __restrict__ bf, const float* __restrict__ bo)
{
    const int idx = blockIdx.x * 256 + threadIdx.x;   // [0, 98304)
    const int b   = idx / (NG * M_ / 4);
    const int c4  = idx % (NG * M_ / 4);
    const int n   = c4 * 4;
    const int gate = n >> 10;
    const int nl   = n & (M_ - 1);

    const float* bias;
    switch (gate) {
        case 0: bias = bq; break;
        case 1: bias = bk; break;
        case 2: bias = bv; break;
        case 3: bias = bi; break;
        case 4: bias = bf; break;
        default: bias = bo; break;
    }

    float4 acc = *(const float4*)&g_part[((size_t)0 * B_ + b) * (NG * M_) + n];
    #pragma unroll
    for (int s = 1; s < NSPLIT; s++) {
        float4 p = *(const float4*)&g_part[((size_t)s * B_ + b) * (NG * M_) + n];
        acc.x += p.x; acc.y += p.y; acc.z += p.z; acc.w += p.w;
    }
    const float4 bv4 = *(const float4*)&bias[nl];
    acc.x += bv4.x; acc.y += bv4.y; acc.z += bv4.z; acc.w += bv4.w;

    if (gate == 1) {
        acc.x *= 0.03125f; acc.y *= 0.03125f; acc.z *= 0.03125f; acc.w *= 0.03125f;
    } else if (gate == 3) {
        acc.x = __expf(acc.x); acc.y = __expf(acc.y);
        acc.z = __expf(acc.z); acc.w = __expf(acc.w);
    } else if (gate >= 4) {
        acc.x = 1.f / (1.f + __expf(-acc.x));
        acc.y = 1.f / (1.f + __expf(-acc.y));
        acc.z = 1.f / (1.f + __expf(-acc.z));
        acc.w = 1.f / (1.f + __expf(-acc.w));
    }
    *(float4*)&g_gates[(size_t)gate * (B_ * M_) + b * M_ + nl] = acc;
}

// ---------------------------------------------------------------------------
// Kernel 2 (fused): C_t update + h_tilde + n_t + denom + h_t.
// grid = (16, 64): blockIdx.y = batch, blockIdx.x = 64-row chunk.
// Prologue (per block, redundant across the 16 blocks of a batch):
//   n_t = f*n_prev + i*k  (block bx==0 writes out_n)
//   denom = max(n_t . q, 1); inv = 1/denom   (block reduce, smem broadcast)
// Main loop: software-pipelined streaming C update, warp-reduced dot with q,
// then lane0 writes h_t[b,m] = o[m] * dot * inv directly.
// ---------------------------------------------------------------------------
__global__ __launch_bounds__(256)
void update_C(const float* __restrict__ Cprev, const float* __restrict__ nprev,
              float* __restrict__ Cout, float* __restrict__ out_h,
              float* __restrict__ out_n)
{
    const int b = blockIdx.y;
    __shared__ float sk[M_];
    __shared__ float sq[M_];
    __shared__ float red[256];
    __shared__ float s_inv;

    const float* gq = g_gates + 0 * (B_ * M_) + b * M_;
    const float* gk = g_gates + 1 * (B_ * M_) + b * M_;
    ((float4*)sk)[threadIdx.x] = ((const float4*)gk)[threadIdx.x];
    ((float4*)sq)[threadIdx.x] = ((const float4*)gq)[threadIdx.x];

    const int warp = threadIdx.x >> 5;
    const int lane = threadIdx.x & 31;
    const float* gv = g_gates + 2 * (B_ * M_) + b * M_;
    const float* gi = g_gates + 3 * (B_ * M_) + b * M_;
    const float* gf = g_gates + 4 * (B_ * M_) + b * M_;
    const float* go = g_gates + 5 * (B_ * M_) + b * M_;

    __syncthreads();

    // --- denom prologue: n_t = f*n_prev + i*k ; part = n_t . q ---
    {
        const int t = threadIdx.x;            // one float4 per thread (1024/4)
        float4 f4 = ((const float4*)gf)[t];
        float4 i4 = ((const float4*)gi)[t];
        float4 p4 = ((const float4*)(nprev + b * M_))[t];
        float4 k4 = ((const float4*)sk)[t];
        float4 q4 = ((const float4*)sq)[t];
        float4 n4;
        n4.x = fmaf(f4.x, p4.x, i4.x * k4.x);
        n4.y = fmaf(f4.y, p4.y, i4.y * k4.y);
        n4.z = fmaf(f4.z, p4.z, i4.z * k4.z);
        n4.w = fmaf(f4.w, p4.w, i4.w * k4.w);
        if (blockIdx.x == 0)
            ((float4*)(out_n + b * M_))[t] = n4;
        float part = n4.x * q4.x + n4.y * q4.y + n4.z * q4.z + n4.w * q4.w;
        #pragma unroll
        for (int off = 16; off; off >>= 1)
            part += __shfl_xor_sync(0xffffffffu, part, off);
        if (lane == 0) red[warp] = part;
        __syncthreads();
        if (threadIdx.x == 0) {
            float d = red[0] + red[1] + red[2] + red[3]
                    + red[4] + red[5] + red[6] + red[7];
            s_inv = 1.0f / fmaxf(d, 1.0f);
        }
        __syncthreads();
    }
    const float inv = s_inv;

    const float4* sk4 = (const float4*)sk;
    const float4* sq4 = (const float4*)sq;

    const int m_base = blockIdx.x * 64 + warp;

    float4 cur[8], nxt[8];
    int m = m_base;
    float fm = gf[m];
    float cm = gi[m] * gv[m];
    {
        const float4* cp = (const float4*)(Cprev + ((size_t)b * M_ + m) * M_);
        #pragma unroll
        for (int j = 0; j < 8; j++) cur[j] = __ldcs(cp + j * 32 + lane);
    }

    #pragma unroll
    for (int r = 0; r < 8; r++) {
        float fmn = 0.f, cmn = 0.f;
        if (r < 7) {
            const int mn = m_base + (r + 1) * 8;
            fmn = gf[mn];
            cmn = gi[mn] * gv[mn];
            const float4* cpn = (const float4*)(Cprev + ((size_t)b * M_ + mn) * M_);
            #pragma unroll
            for (int j = 0; j < 8; j++) nxt[j] = __ldcs(cpn + j * 32 + lane);
        }

        float4* co = (float4*)(Cout + ((size_t)b * M_ + m) * M_);
        float dot0 = 0.f, dot1 = 0.f;
        #pragma unroll
        for (int j = 0; j < 8; j++) {
            const int n4 = j * 32 + lane;
            float4 kk = sk4[n4];
            float4 qq = sq4[n4];
            float4 o;
            o.x = fmaf(fm, cur[j].x, cm * kk.x);
            o.y = fmaf(fm, cur[j].y, cm * kk.y);
            o.z = fmaf(fm, cur[j].z, cm * kk.z);
            o.w = fmaf(fm, cur[j].w, cm * kk.w);
            __stcs(co + n4, o);
            if (j & 1) {
                dot1 = fmaf(o.x, qq.x, dot1);
                dot1 = fmaf(o.y, qq.y, dot1);
                dot1 = fmaf(o.z, qq.z, dot1);
                dot1 = fmaf(o.w, qq.w, dot1);
            } else {
                dot0 = fmaf(o.x, qq.x, dot0);
                dot0 = fmaf(o.y, qq.y, dot0);
                dot0 = fmaf(o.z, qq.z, dot0);
                dot0 = fmaf(o.w, qq.w, dot0);
            }
        }
        float dot = dot0 + dot1;
        #pragma unroll
        for (int off = 16; off; off >>= 1)
            dot += __shfl_xor_sync(0xffffffffu, dot, off);
        if (lane == 0)
            out_h[b * M_ + m] = go[m] * dot * inv;

        m = m_base + (r + 1) * 8;
        fm = fmn;
        cm = cmn;
        #pragma unroll
        for (int j = 0; j < 8; j++) cur[j] = nxt[j];
    }
}

// ---------------------------------------------------------------------------
// Launch. Inputs (metadata order):
// 0 x, 1 h_prev, 2 c_prev, 3 C_prev, 4 n_prev, 5 m_prev,
// 6 Wq, 7 bq, 8 Wk, 9 bk, 10 Wv, 11 bv, 12 Wi, 13 bi, 14 Wf, 15 bf, 16 Wo, 17 bo
// Output: concat(h_t [64*1024], C_t [64*1024*1024], n_t [64*1024])
// ---------------------------------------------------------------------------
extern "C" void kernel_launch(void* const* d_in, const int* in_sizes, int n_in,
                              void* d_out, int out_size)
{
    const float* x     = (const float*)d_in[0];
    const float* Cprev = (const float*)d_in[3];
    const float* nprev = (const float*)d_in[4];

    const float* Wq = (const float*)d_in[6];  const float* bq = (const float*)d_in[7];
    const float* Wk = (const float*)d_in[8];  const float* bk = (const float*)d_in[9];
    const float* Wv = (const float*)d_in[10]; const float* bv = (const float*)d_in[11];
    const float* Wi = (const float*)d_in[12]; const float* bi = (const float*)d_in[13];
    const float* Wf = (const float*)d_in[14]; const float* bf = (const float*)d_in[15];
    const float* Wo = (const float*)d_in[16]; const float* bo = (const float*)d_in[17];

    float* out   = (float*)d_out;
    float* out_h = out;                                    // [64*1024]
    float* out_C = out + (size_t)B_ * M_;                  // [64*1024*1024]
    float* out_n = out + (size_t)B_ * M_ + (size_t)B_ * M_ * M_;

    dim3 grid1(96, NSPLIT);
    gates_gemm_sk<<<grid1, 256>>>(x, Wq, Wk, Wv, Wi, Wf, Wo);

    gates_reduce<<<384, 256>>>(bq, bk, bv, bi, bf, bo);

    dim3 grid2(16, 64);
    update_C<<<grid2, 256>>>(Cprev, nprev, out_C, out_h, out_n);
}

// round 7
// speedup vs baseline: 1.1625x; 1.0471x over previous
#include <cuda_runtime.h>
#include <math.h>
#include <stdint.h>

// Problem constants
#define B_   64
#define IN_  512
#define M_   1024
#define NG   6          // q,k,v,i,f,o

// gate scratch layout: [gate][b][m]
__device__ float g_gates[NG * B_ * M_];

// ---------------------------------------------------------------------------
// TF32 helpers
// ---------------------------------------------------------------------------
__device__ __forceinline__ uint32_t f2tf32(float f) {
    uint32_t u;
    asm("cvt.rna.tf32.f32 %0, %1;" : "=r"(u) : "f"(f));
    return u;
}

__device__ __forceinline__ void mma_tf32(float* c, const uint32_t* a, const uint32_t* b) {
    asm("mma.sync.aligned.m16n8k8.row.col.f32.tf32.tf32.f32 "
        "{%0,%1,%2,%3},{%4,%5,%6,%7},{%8,%9},{%0,%1,%2,%3};"
        : "+f"(c[0]), "+f"(c[1]), "+f"(c[2]), "+f"(c[3])
        : "r"(a[0]), "r"(a[1]), "r"(a[2]), "r"(a[3]),
          "r"(b[0]), "r"(b[1]));
}

__device__ __forceinline__ float gate_act(float v, int gate) {
    if (gate == 1) return v * 0.03125f;                 // k: 1/sqrt(1024)
    if (gate == 3) return __expf(v);                    // i: exp
    if (gate >= 4) return 1.f / (1.f + __expf(-v));     // f,o: sigmoid
    return v;                                           // q,v
}

// ---------------------------------------------------------------------------
// Kernel 1: fused 6-gate GEMM via TF32 tensor cores.
//   out[g,b,n] = act_g( x[b,:] . W_g[n,:] + bias_g[n] )
// grid = 96 (one 64-col tile each, entirely within one gate), 256 threads.
// Block tile BM=64 (all batches) x BN=64 x BK=32, double-buffered smem.
// Warp grid 2(m) x 4(n): warp tile 32x16 = 2 m16-tiles x 2 n8-tiles.
// smem stride 36 words -> fragment loads are bank-conflict-free
// (bank = 4*groupID + tid_in_group, unique over the warp).
// Bias + activation fused in the epilogue; writes g_gates directly.
// ---------------------------------------------------------------------------
__global__ __launch_bounds__(256)
void gates_mma(const float* __restrict__ x,
               const float* __restrict__ Wq, const float* __restrict__ bq,
               const float* __restrict__ Wk, const float* __restrict__ bk,
               const float* __restrict__ Wv, const float* __restrict__ bv,
               const float* __restrict__ Wi, const float* __restrict__ bi,
               const float* __restrict__ Wf, const float* __restrict__ bf,
               const float* __restrict__ Wo, const float* __restrict__ bo)
{
    const int n_global0 = blockIdx.x * 64;          // [0, 6144)
    const int gate      = n_global0 >> 10;          // 0..5
    const int n_local0  = n_global0 & (M_ - 1);

    const float* W; const float* bias;
    switch (gate) {
        case 0: W = Wq; bias = bq; break;
        case 1: W = Wk; bias = bk; break;
        case 2: W = Wv; bias = bv; break;
        case 3: W = Wi; bias = bi; break;
        case 4: W = Wf; bias = bf; break;
        default: W = Wo; bias = bo; break;
    }

    __shared__ uint32_t Xs[2][64][36];   // [buf][b][k] tf32 bits
    __shared__ uint32_t Ws[2][64][36];   // [buf][n][k] tf32 bits

    const int tid  = threadIdx.x;
    const int wid  = tid >> 5;
    const int lane = tid & 31;
    const int g    = lane >> 2;        // groupID 0..7
    const int tig  = lane & 3;         // thread-in-group 0..3
    const int warp_m = wid & 1;        // 0..1 -> 32 rows each
    const int warp_n = wid >> 1;       // 0..3 -> 16 cols each

    // global-load mapping: 512 float4 per 64x32 tile, 2 per thread
    const int lrow0 = tid >> 3;          // 0..31
    const int lrow1 = lrow0 + 32;        // 32..63
    const int lcol  = (tid & 7) * 4;     // 0,4,...,28

    const float* xg0 = x + lrow0 * IN_ + lcol;
    const float* xg1 = x + lrow1 * IN_ + lcol;
    const float* wg0 = W + (n_local0 + lrow0) * IN_ + lcol;
    const float* wg1 = W + (n_local0 + lrow1) * IN_ + lcol;

    float acc[2][2][4];
    #pragma unroll
    for (int mt = 0; mt < 2; mt++)
        #pragma unroll
        for (int nt = 0; nt < 2; nt++)
            #pragma unroll
            for (int e = 0; e < 4; e++) acc[mt][nt][e] = 0.f;

    float4 xr0, xr1, wr0, wr1;
    xr0 = *(const float4*)xg0;
    xr1 = *(const float4*)xg1;
    wr0 = *(const float4*)wg0;
    wr1 = *(const float4*)wg1;

    // store tile 0 (convert to tf32 on the way in)
    {
        uint4 u;
        u.x = f2tf32(xr0.x); u.y = f2tf32(xr0.y); u.z = f2tf32(xr0.z); u.w = f2tf32(xr0.w);
        *(uint4*)&Xs[0][lrow0][lcol] = u;
        u.x = f2tf32(xr1.x); u.y = f2tf32(xr1.y); u.z = f2tf32(xr1.z); u.w = f2tf32(xr1.w);
        *(uint4*)&Xs[0][lrow1][lcol] = u;
        u.x = f2tf32(wr0.x); u.y = f2tf32(wr0.y); u.z = f2tf32(wr0.z); u.w = f2tf32(wr0.w);
        *(uint4*)&Ws[0][lrow0][lcol] = u;
        u.x = f2tf32(wr1.x); u.y = f2tf32(wr1.y); u.z = f2tf32(wr1.z); u.w = f2tf32(wr1.w);
        *(uint4*)&Ws[0][lrow1][lcol] = u;
    }
    __syncthreads();

    int buf = 0;
    #pragma unroll 1
    for (int it = 0; it < IN_ / 32; it++) {
        // prefetch next tile (overlaps with mma below)
        if (it < IN_ / 32 - 1) {
            const int k0 = (it + 1) * 32;
            xr0 = *(const float4*)(xg0 + k0);
            xr1 = *(const float4*)(xg1 + k0);
            wr0 = *(const float4*)(wg0 + k0);
            wr1 = *(const float4*)(wg1 + k0);
        }

        #pragma unroll
        for (int ks = 0; ks < 4; ks++) {
            const int ko = ks * 8;
            uint32_t af[2][4];
            #pragma unroll
            for (int mt = 0; mt < 2; mt++) {
                const int r = warp_m * 32 + mt * 16 + g;
                af[mt][0] = Xs[buf][r][ko + tig];
                af[mt][1] = Xs[buf][r + 8][ko + tig];
                af[mt][2] = Xs[buf][r][ko + tig + 4];
                af[mt][3] = Xs[buf][r + 8][ko + tig + 4];
            }
            uint32_t bfr[2][2];
            #pragma unroll
            for (int nt = 0; nt < 2; nt++) {
                const int c = warp_n * 16 + nt * 8 + g;
                bfr[nt][0] = Ws[buf][c][ko + tig];
                bfr[nt][1] = Ws[buf][c][ko + tig + 4];
            }
            #pragma unroll
            for (int mt = 0; mt < 2; mt++)
                #pragma unroll
                for (int nt = 0; nt < 2; nt++)
                    mma_tf32(acc[mt][nt], af[mt], bfr[nt]);
        }

        if (it < IN_ / 32 - 1) {
            const int nb = buf ^ 1;
            uint4 u;
            u.x = f2tf32(xr0.x); u.y = f2tf32(xr0.y); u.z = f2tf32(xr0.z); u.w = f2tf32(xr0.w);
            *(uint4*)&Xs[nb][lrow0][lcol] = u;
            u.x = f2tf32(xr1.x); u.y = f2tf32(xr1.y); u.z = f2tf32(xr1.z); u.w = f2tf32(xr1.w);
            *(uint4*)&Xs[nb][lrow1][lcol] = u;
            u.x = f2tf32(wr0.x); u.y = f2tf32(wr0.y); u.z = f2tf32(wr0.z); u.w = f2tf32(wr0.w);
            *(uint4*)&Ws[nb][lrow0][lcol] = u;
            u.x = f2tf32(wr1.x); u.y = f2tf32(wr1.y); u.z = f2tf32(wr1.z); u.w = f2tf32(wr1.w);
            *(uint4*)&Ws[nb][lrow1][lcol] = u;
            __syncthreads();
            buf = nb;
        }
    }

    // epilogue: bias + activation, write gates directly
    float* outg = g_gates + (size_t)gate * (B_ * M_);
    #pragma unroll
    for (int mt = 0; mt < 2; mt++) {
        const int r0 = warp_m * 32 + mt * 16 + g;   // batch row
        #pragma unroll
        for (int nt = 0; nt < 2; nt++) {
            const int ncol = n_local0 + warp_n * 16 + nt * 8 + 2 * tig;
            const float b0 = bias[ncol];
            const float b1 = bias[ncol + 1];
            float2 v0, v1;
            v0.x = gate_act(acc[mt][nt][0] + b0, gate);
            v0.y = gate_act(acc[mt][nt][1] + b1, gate);
            v1.x = gate_act(acc[mt][nt][2] + b0, gate);
            v1.y = gate_act(acc[mt][nt][3] + b1, gate);
            *(float2*)&outg[r0 * M_ + ncol] = v0;
            *(float2*)&outg[(r0 + 8) * M_ + ncol] = v1;
        }
    }
}

// ---------------------------------------------------------------------------
// Kernel 2 (fused): C_t update + h_tilde + n_t + denom + h_t.
// grid = (16, 64): blockIdx.y = batch, blockIdx.x = 64-row chunk.
// Prologue (redundant per block): n_t = f*n_prev + i*k (bx==0 writes out_n),
// denom = max(n_t.q, 1). Main loop: software-pipelined streaming C update,
// warp-reduced dot with q, lane0 writes h_t[b,m] = o[m]*dot/denom.
// ---------------------------------------------------------------------------
__global__ __launch_bounds__(256)
void update_C(const float* __restrict__ Cprev, const float* __restrict__ nprev,
              float* __restrict__ Cout, float* __restrict__ out_h,
              float* __restrict__ out_n)
{
    const int b = blockIdx.y;
    __shared__ float sk[M_];
    __shared__ float sq[M_];
    __shared__ float red[8];
    __shared__ float s_inv;

    const float* gq = g_gates + 0 * (B_ * M_) + b * M_;
    const float* gk = g_gates + 1 * (B_ * M_) + b * M_;
    ((float4*)sk)[threadIdx.x] = ((const float4*)gk)[threadIdx.x];
    ((float4*)sq)[threadIdx.x] = ((const float4*)gq)[threadIdx.x];

    const int warp = threadIdx.x >> 5;
    const int lane = threadIdx.x & 31;
    const float* gv = g_gates + 2 * (B_ * M_) + b * M_;
    const float* gi = g_gates + 3 * (B_ * M_) + b * M_;
    const float* gf = g_gates + 4 * (B_ * M_) + b * M_;
    const float* go = g_gates + 5 * (B_ * M_) + b * M_;

    __syncthreads();

    // --- denom prologue: n_t = f*n_prev + i*k ; part = n_t . q ---
    {
        const int t = threadIdx.x;            // one float4 per thread
        float4 f4 = ((const float4*)gf)[t];
        float4 i4 = ((const float4*)gi)[t];
        float4 p4 = ((const float4*)(nprev + b * M_))[t];
        float4 k4 = ((const float4*)sk)[t];
        float4 q4 = ((const float4*)sq)[t];
        float4 n4;
        n4.x = fmaf(f4.x, p4.x, i4.x * k4.x);
        n4.y = fmaf(f4.y, p4.y, i4.y * k4.y);
        n4.z = fmaf(f4.z, p4.z, i4.z * k4.z);
        n4.w = fmaf(f4.w, p4.w, i4.w * k4.w);
        if (blockIdx.x == 0)
            ((float4*)(out_n + b * M_))[t] = n4;
        float part = n4.x * q4.x + n4.y * q4.y + n4.z * q4.z + n4.w * q4.w;
        #pragma unroll
        for (int off = 16; off; off >>= 1)
            part += __shfl_xor_sync(0xffffffffu, part, off);
        if (lane == 0) red[warp] = part;
        __syncthreads();
        if (threadIdx.x == 0) {
            float d = red[0] + red[1] + red[2] + red[3]
                    + red[4] + red[5] + red[6] + red[7];
            s_inv = 1.0f / fmaxf(d, 1.0f);
        }
        __syncthreads();
    }
    const float inv = s_inv;

    const float4* sk4 = (const float4*)sk;
    const float4* sq4 = (const float4*)sq;

    const int m_base = blockIdx.x * 64 + warp;

    float4 cur[8], nxt[8];
    int m = m_base;
    float fm = gf[m];
    float cm = gi[m] * gv[m];
    {
        const float4* cp = (const float4*)(Cprev + ((size_t)b * M_ + m) * M_);
        #pragma unroll
        for (int j = 0; j < 8; j++) cur[j] = __ldcs(cp + j * 32 + lane);
    }

    #pragma unroll
    for (int r = 0; r < 8; r++) {
        float fmn = 0.f, cmn = 0.f;
        if (r < 7) {
            const int mn = m_base + (r + 1) * 8;
            fmn = gf[mn];
            cmn = gi[mn] * gv[mn];
            const float4* cpn = (const float4*)(Cprev + ((size_t)b * M_ + mn) * M_);
            #pragma unroll
            for (int j = 0; j < 8; j++) nxt[j] = __ldcs(cpn + j * 32 + lane);
        }

        float4* co = (float4*)(Cout + ((size_t)b * M_ + m) * M_);
        float dot0 = 0.f, dot1 = 0.f;
        #pragma unroll
        for (int j = 0; j < 8; j++) {
            const int n4 = j * 32 + lane;
            float4 kk = sk4[n4];
            float4 qq = sq4[n4];
            float4 o;
            o.x = fmaf(fm, cur[j].x, cm * kk.x);
            o.y = fmaf(fm, cur[j].y, cm * kk.y);
            o.z = fmaf(fm, cur[j].z, cm * kk.z);
            o.w = fmaf(fm, cur[j].w, cm * kk.w);
            __stcs(co + n4, o);
            if (j & 1) {
                dot1 = fmaf(o.x, qq.x, dot1);
                dot1 = fmaf(o.y, qq.y, dot1);
                dot1 = fmaf(o.z, qq.z, dot1);
                dot1 = fmaf(o.w, qq.w, dot1);
            } else {
                dot0 = fmaf(o.x, qq.x, dot0);
                dot0 = fmaf(o.y, qq.y, dot0);
                dot0 = fmaf(o.z, qq.z, dot0);
                dot0 = fmaf(o.w, qq.w, dot0);
            }
        }
        float dot = dot0 + dot1;
        #pragma unroll
        for (int off = 16; off; off >>= 1)
            dot += __shfl_xor_sync(0xffffffffu, dot, off);
        if (lane == 0)
            out_h[b * M_ + m] = go[m] * dot * inv;

        m = m_base + (r + 1) * 8;
        fm = fmn;
        cm = cmn;
        #pragma unroll
        for (int j = 0; j < 8; j++) cur[j] = nxt[j];
    }
}

// ---------------------------------------------------------------------------
// Launch. Inputs (metadata order):
// 0 x, 1 h_prev, 2 c_prev, 3 C_prev, 4 n_prev, 5 m_prev,
// 6 Wq, 7 bq, 8 Wk, 9 bk, 10 Wv, 11 bv, 12 Wi, 13 bi, 14 Wf, 15 bf, 16 Wo, 17 bo
// Output: concat(h_t [64*1024], C_t [64*1024*1024], n_t [64*1024])
// ---------------------------------------------------------------------------
extern "C" void kernel_launch(void* const* d_in, const int* in_sizes, int n_in,
                              void* d_out, int out_size)
{
    const float* x     = (const float*)d_in[0];
    const float* Cprev = (const float*)d_in[3];
    const float* nprev = (const float*)d_in[4];

    const float* Wq = (const float*)d_in[6];  const float* bq = (const float*)d_in[7];
    const float* Wk = (const float*)d_in[8];  const float* bk = (const float*)d_in[9];
    const float* Wv = (const float*)d_in[10]; const float* bv = (const float*)d_in[11];
    const float* Wi = (const float*)d_in[12]; const float* bi = (const float*)d_in[13];
    const float* Wf = (const float*)d_in[14]; const float* bf = (const float*)d_in[15];
    const float* Wo = (const float*)d_in[16]; const float* bo = (const float*)d_in[17];

    float* out   = (float*)d_out;
    float* out_h = out;                                    // [64*1024]
    float* out_C = out + (size_t)B_ * M_;                  // [64*1024*1024]
    float* out_n = out + (size_t)B_ * M_ + (size_t)B_ * M_ * M_;

    gates_mma<<<96, 256>>>(x, Wq, bq, Wk, bk, Wv, bv, Wi, bi, Wf, bf, Wo, bo);

    dim3 grid2(16, 64);
    update_C<<<grid2, 256>>>(Cprev, nprev, out_C, out_h, out_n);
}

// round 8
// speedup vs baseline: 1.1821x; 1.0168x over previous
#include <cuda_runtime.h>
#include <math.h>
#include <stdint.h>

// Problem constants
#define B_   64
#define IN_  512
#define M_   1024
#define NG   6          // q,k,v,i,f,o
#define NSPLIT 4
#define KSL  (IN_ / NSPLIT)   // 128

// scratch
__device__ float g_gates[NG * B_ * M_];          // [gate][b][m]
__device__ float g_part[NSPLIT * B_ * NG * M_];  // [s][b][n_global]

// ---------------------------------------------------------------------------
// TF32 helpers
// ---------------------------------------------------------------------------
__device__ __forceinline__ uint32_t f2tf32(float f) {
    uint32_t u;
    asm("cvt.rna.tf32.f32 %0, %1;" : "=r"(u) : "f"(f));
    return u;
}

__device__ __forceinline__ void mma_tf32(float* c, const uint32_t* a, const uint32_t* b) {
    asm("mma.sync.aligned.m16n8k8.row.col.f32.tf32.tf32.f32 "
        "{%0,%1,%2,%3},{%4,%5,%6,%7},{%8,%9},{%0,%1,%2,%3};"
        : "+f"(c[0]), "+f"(c[1]), "+f"(c[2]), "+f"(c[3])
        : "r"(a[0]), "r"(a[1]), "r"(a[2]), "r"(a[3]),
          "r"(b[0]), "r"(b[1]));
}

// ---------------------------------------------------------------------------
// Kernel 1a: split-K TF32 tensor-core GEMM partials.
// grid = (96, 4): bx -> 64-wide column tile, by -> K slice (128 wide).
// Block tile BM=64 x BN=64 x BK=32, double-buffered smem, warp grid 2m x 4n.
// partial[s][b][n_global] = sum_{k in slice} x[b,k] * W[n,k]
// ---------------------------------------------------------------------------
__global__ __launch_bounds__(256)
void gates_mma_sk(const float* __restrict__ x,
                  const float* __restrict__ Wq, const float* __restrict__ Wk,
                  const float* __restrict__ Wv, const float* __restrict__ Wi,
                  const float* __restrict__ Wf, const float* __restrict__ Wo)
{
    const int n_global0 = blockIdx.x * 64;          // [0, 6144)
    const int gate      = n_global0 >> 10;
    const int n_local0  = n_global0 & (M_ - 1);
    const int s         = blockIdx.y;
    const int k_base    = s * KSL;

    const float* W;
    switch (gate) {
        case 0: W = Wq; break;
        case 1: W = Wk; break;
        case 2: W = Wv; break;
        case 3: W = Wi; break;
        case 4: W = Wf; break;
        default: W = Wo; break;
    }

    __shared__ uint32_t Xs[2][64][36];   // [buf][b][k] tf32 bits
    __shared__ uint32_t Ws[2][64][36];   // [buf][n][k] tf32 bits

    const int tid  = threadIdx.x;
    const int wid  = tid >> 5;
    const int lane = tid & 31;
    const int g    = lane >> 2;        // groupID 0..7
    const int tig  = lane & 3;         // thread-in-group 0..3
    const int warp_m = wid & 1;        // 32 rows each
    const int warp_n = wid >> 1;       // 16 cols each

    const int lrow0 = tid >> 3;          // 0..31
    const int lrow1 = lrow0 + 32;
    const int lcol  = (tid & 7) * 4;

    const float* xg0 = x + lrow0 * IN_ + k_base + lcol;
    const float* xg1 = x + lrow1 * IN_ + k_base + lcol;
    const float* wg0 = W + (n_local0 + lrow0) * IN_ + k_base + lcol;
    const float* wg1 = W + (n_local0 + lrow1) * IN_ + k_base + lcol;

    float acc[2][2][4];
    #pragma unroll
    for (int mt = 0; mt < 2; mt++)
        #pragma unroll
        for (int nt = 0; nt < 2; nt++)
            #pragma unroll
            for (int e = 0; e < 4; e++) acc[mt][nt][e] = 0.f;

    float4 xr0, xr1, wr0, wr1;
    xr0 = *(const float4*)xg0;
    xr1 = *(const float4*)xg1;
    wr0 = *(const float4*)wg0;
    wr1 = *(const float4*)wg1;

    {
        uint4 u;
        u.x = f2tf32(xr0.x); u.y = f2tf32(xr0.y); u.z = f2tf32(xr0.z); u.w = f2tf32(xr0.w);
        *(uint4*)&Xs[0][lrow0][lcol] = u;
        u.x = f2tf32(xr1.x); u.y = f2tf32(xr1.y); u.z = f2tf32(xr1.z); u.w = f2tf32(xr1.w);
        *(uint4*)&Xs[0][lrow1][lcol] = u;
        u.x = f2tf32(wr0.x); u.y = f2tf32(wr0.y); u.z = f2tf32(wr0.z); u.w = f2tf32(wr0.w);
        *(uint4*)&Ws[0][lrow0][lcol] = u;
        u.x = f2tf32(wr1.x); u.y = f2tf32(wr1.y); u.z = f2tf32(wr1.z); u.w = f2tf32(wr1.w);
        *(uint4*)&Ws[0][lrow1][lcol] = u;
    }
    __syncthreads();

    int buf = 0;
    #pragma unroll 1
    for (int it = 0; it < KSL / 32; it++) {
        if (it < KSL / 32 - 1) {
            const int k0 = (it + 1) * 32;
            xr0 = *(const float4*)(xg0 + k0);
            xr1 = *(const float4*)(xg1 + k0);
            wr0 = *(const float4*)(wg0 + k0);
            wr1 = *(const float4*)(wg1 + k0);
        }

        #pragma unroll
        for (int ks = 0; ks < 4; ks++) {
            const int ko = ks * 8;
            uint32_t af[2][4];
            #pragma unroll
            for (int mt = 0; mt < 2; mt++) {
                const int r = warp_m * 32 + mt * 16 + g;
                af[mt][0] = Xs[buf][r][ko + tig];
                af[mt][1] = Xs[buf][r + 8][ko + tig];
                af[mt][2] = Xs[buf][r][ko + tig + 4];
                af[mt][3] = Xs[buf][r + 8][ko + tig + 4];
            }
            uint32_t bfr[2][2];
            #pragma unroll
            for (int nt = 0; nt < 2; nt++) {
                const int c = warp_n * 16 + nt * 8 + g;
                bfr[nt][0] = Ws[buf][c][ko + tig];
                bfr[nt][1] = Ws[buf][c][ko + tig + 4];
            }
            #pragma unroll
            for (int mt = 0; mt < 2; mt++)
                #pragma unroll
                for (int nt = 0; nt < 2; nt++)
                    mma_tf32(acc[mt][nt], af[mt], bfr[nt]);
        }

        if (it < KSL / 32 - 1) {
            const int nb = buf ^ 1;
            uint4 u;
            u.x = f2tf32(xr0.x); u.y = f2tf32(xr0.y); u.z = f2tf32(xr0.z); u.w = f2tf32(xr0.w);
            *(uint4*)&Xs[nb][lrow0][lcol] = u;
            u.x = f2tf32(xr1.x); u.y = f2tf32(xr1.y); u.z = f2tf32(xr1.z); u.w = f2tf32(xr1.w);
            *(uint4*)&Xs[nb][lrow1][lcol] = u;
            u.x = f2tf32(wr0.x); u.y = f2tf32(wr0.y); u.z = f2tf32(wr0.z); u.w = f2tf32(wr0.w);
            *(uint4*)&Ws[nb][lrow0][lcol] = u;
            u.x = f2tf32(wr1.x); u.y = f2tf32(wr1.y); u.z = f2tf32(wr1.z); u.w = f2tf32(wr1.w);
            *(uint4*)&Ws[nb][lrow1][lcol] = u;
            __syncthreads();
            buf = nb;
        }
    }

    // write raw partials (L2-resident)
    float* outp = g_part + (size_t)s * (B_ * NG * M_);
    #pragma unroll
    for (int mt = 0; mt < 2; mt++) {
        const int r0 = warp_m * 32 + mt * 16 + g;   // batch row
        #pragma unroll
        for (int nt = 0; nt < 2; nt++) {
            const int ncol = n_global0 + warp_n * 16 + nt * 8 + 2 * tig;
            *(float2*)&outp[(size_t)r0 * (NG * M_) + ncol] =
                make_float2(acc[mt][nt][0], acc[mt][nt][1]);
            *(float2*)&outp[(size_t)(r0 + 8) * (NG * M_) + ncol] =
                make_float2(acc[mt][nt][2], acc[mt][nt][3]);
        }
    }
}

// ---------------------------------------------------------------------------
// Kernel 1b: reduce partials + bias + activation -> g_gates[gate][b][m]
// ---------------------------------------------------------------------------
__global__ __launch_bounds__(256)
void gates_reduce(const float* __restrict__ bq, const float* __restrict__ bk,
                  const float* __restrict__ bv, const float* __restrict__ bi,
                  const float* __restrict__ bf, const float* __restrict__ bo)
{
    const int idx = blockIdx.x * 256 + threadIdx.x;   // [0, 98304)
    const int b   = idx / (NG * M_ / 4);
    const int c4  = idx % (NG * M_ / 4);
    const int n   = c4 * 4;
    const int gate = n >> 10;
    const int nl   = n & (M_ - 1);

    const float* bias;
    switch (gate) {
        case 0: bias = bq; break;
        case 1: bias = bk; break;
        case 2: bias = bv; break;
        case 3: bias = bi; break;
        case 4: bias = bf; break;
        default: bias = bo; break;
    }

    float4 acc = *(const float4*)&g_part[((size_t)0 * B_ + b) * (NG * M_) + n];
    #pragma unroll
    for (int s = 1; s < NSPLIT; s++) {
        float4 p = *(const float4*)&g_part[((size_t)s * B_ + b) * (NG * M_) + n];
        acc.x += p.x; acc.y += p.y; acc.z += p.z; acc.w += p.w;
    }
    const float4 bv4 = *(const float4*)&bias[nl];
    acc.x += bv4.x; acc.y += bv4.y; acc.z += bv4.z; acc.w += bv4.w;

    if (gate == 1) {
        acc.x *= 0.03125f; acc.y *= 0.03125f; acc.z *= 0.03125f; acc.w *= 0.03125f;
    } else if (gate == 3) {
        acc.x = __expf(acc.x); acc.y = __expf(acc.y);
        acc.z = __expf(acc.z); acc.w = __expf(acc.w);
    } else if (gate >= 4) {
        acc.x = 1.f / (1.f + __expf(-acc.x));
        acc.y = 1.f / (1.f + __expf(-acc.y));
        acc.z = 1.f / (1.f + __expf(-acc.z));
        acc.w = 1.f / (1.f + __expf(-acc.w));
    }
    *(float4*)&g_gates[(size_t)gate * (B_ * M_) + b * M_ + nl] = acc;
}

// ---------------------------------------------------------------------------
// Kernel 2 (fused): C_t update + h_tilde + n_t + denom + h_t.
// grid = (16, 64). NO cross-row pipeline (cuts ~32 regs) and
// __launch_bounds__(256, 3) to force 3 blocks/SM (24 warps) — more
// outstanding loads overall than the 2-block pipelined version.
// ---------------------------------------------------------------------------
__global__ __launch_bounds__(256, 3)
void update_C(const float* __restrict__ Cprev, const float* __restrict__ nprev,
              float* __restrict__ Cout, float* __restrict__ out_h,
              float* __restrict__ out_n)
{
    const int b = blockIdx.y;
    __shared__ float sk[M_];
    __shared__ float sq[M_];
    __shared__ float red[8];
    __shared__ float s_inv;

    const float* gq = g_gates + 0 * (B_ * M_) + b * M_;
    const float* gk = g_gates + 1 * (B_ * M_) + b * M_;
    ((float4*)sk)[threadIdx.x] = ((const float4*)gk)[threadIdx.x];
    ((float4*)sq)[threadIdx.x] = ((const float4*)gq)[threadIdx.x];

    const int warp = threadIdx.x >> 5;
    const int lane = threadIdx.x & 31;
    const float* gv = g_gates + 2 * (B_ * M_) + b * M_;
    const float* gi = g_gates + 3 * (B_ * M_) + b * M_;
    const float* gf = g_gates + 4 * (B_ * M_) + b * M_;
    const float* go = g_gates + 5 * (B_ * M_) + b * M_;

    __syncthreads();

    // --- denom prologue: n_t = f*n_prev + i*k ; part = n_t . q ---
    {
        const int t = threadIdx.x;
        float4 f4 = ((const float4*)gf)[t];
        float4 i4 = ((const float4*)gi)[t];
        float4 p4 = ((const float4*)(nprev + b * M_))[t];
        float4 k4 = ((const float4*)sk)[t];
        float4 q4 = ((const float4*)sq)[t];
        float4 n4;
        n4.x = fmaf(f4.x, p4.x, i4.x * k4.x);
        n4.y = fmaf(f4.y, p4.y, i4.y * k4.y);
        n4.z = fmaf(f4.z, p4.z, i4.z * k4.z);
        n4.w = fmaf(f4.w, p4.w, i4.w * k4.w);
        if (blockIdx.x == 0)
            ((float4*)(out_n + b * M_))[t] = n4;
        float part = n4.x * q4.x + n4.y * q4.y + n4.z * q4.z + n4.w * q4.w;
        #pragma unroll
        for (int off = 16; off; off >>= 1)
            part += __shfl_xor_sync(0xffffffffu, part, off);
        if (lane == 0) red[warp] = part;
        __syncthreads();
        if (threadIdx.x == 0) {
            float d = red[0] + red[1] + red[2] + red[3]
                    + red[4] + red[5] + red[6] + red[7];
            s_inv = 1.0f / fmaxf(d, 1.0f);
        }
        __syncthreads();
    }
    const float inv = s_inv;

    const float4* sk4 = (const float4*)sk;
    const float4* sq4 = (const float4*)sq;

    #pragma unroll
    for (int r = 0; r < 8; r++) {
        const int m = blockIdx.x * 64 + r * 8 + warp;
        const float fm = gf[m];
        const float cm = gi[m] * gv[m];

        const float4* cp = (const float4*)(Cprev + ((size_t)b * M_ + m) * M_);
        float4*       co = (float4*)(Cout  + ((size_t)b * M_ + m) * M_);

        // issue the whole row's loads first: MLP = 8
        float4 c[8];
        #pragma unroll
        for (int j = 0; j < 8; j++)
            c[j] = __ldcs(cp + j * 32 + lane);

        float dot0 = 0.f, dot1 = 0.f;
        #pragma unroll
        for (int j = 0; j < 8; j++) {
            const int n4 = j * 32 + lane;
            float4 kk = sk4[n4];
            float4 qq = sq4[n4];
            float4 o;
            o.x = fmaf(fm, c[j].x, cm * kk.x);
            o.y = fmaf(fm, c[j].y, cm * kk.y);
            o.z = fmaf(fm, c[j].z, cm * kk.z);
            o.w = fmaf(fm, c[j].w, cm * kk.w);
            __stcs(co + n4, o);
            if (j & 1) {
                dot1 = fmaf(o.x, qq.x, dot1);
                dot1 = fmaf(o.y, qq.y, dot1);
                dot1 = fmaf(o.z, qq.z, dot1);
                dot1 = fmaf(o.w, qq.w, dot1);
            } else {
                dot0 = fmaf(o.x, qq.x, dot0);
                dot0 = fmaf(o.y, qq.y, dot0);
                dot0 = fmaf(o.z, qq.z, dot0);
                dot0 = fmaf(o.w, qq.w, dot0);
            }
        }
        float dot = dot0 + dot1;
        #pragma unroll
        for (int off = 16; off; off >>= 1)
            dot += __shfl_xor_sync(0xffffffffu, dot, off);
        if (lane == 0)
            out_h[b * M_ + m] = go[m] * dot * inv;
    }
}

// ---------------------------------------------------------------------------
// Launch. Inputs (metadata order):
// 0 x, 1 h_prev, 2 c_prev, 3 C_prev, 4 n_prev, 5 m_prev,
// 6 Wq, 7 bq, 8 Wk, 9 bk, 10 Wv, 11 bv, 12 Wi, 13 bi, 14 Wf, 15 bf, 16 Wo, 17 bo
// Output: concat(h_t [64*1024], C_t [64*1024*1024], n_t [64*1024])
// ---------------------------------------------------------------------------
extern "C" void kernel_launch(void* const* d_in, const int* in_sizes, int n_in,
                              void* d_out, int out_size)
{
    const float* x     = (const float*)d_in[0];
    const float* Cprev = (const float*)d_in[3];
    const float* nprev = (const float*)d_in[4];

    const float* Wq = (const float*)d_in[6];  const float* bq = (const float*)d_in[7];
    const float* Wk = (const float*)d_in[8];  const float* bk = (const float*)d_in[9];
    const float* Wv = (const float*)d_in[10]; const float* bv = (const float*)d_in[11];
    const float* Wi = (const float*)d_in[12]; const float* bi = (const float*)d_in[13];
    const float* Wf = (const float*)d_in[14]; const float* bf = (const float*)d_in[15];
    const float* Wo = (const float*)d_in[16]; const float* bo = (const float*)d_in[17];

    float* out   = (float*)d_out;
    float* out_h = out;                                    // [64*1024]
    float* out_C = out + (size_t)B_ * M_;                  // [64*1024*1024]
    float* out_n = out + (size_t)B_ * M_ + (size_t)B_ * M_ * M_;

    dim3 grid1(96, NSPLIT);
    gates_mma_sk<<<grid1, 256>>>(x, Wq, Wk, Wv, Wi, Wf, Wo);

    gates_reduce<<<384, 256>>>(bq, bk, bv, bi, bf, bo);

    dim3 grid2(16, 64);
    update_C<<<grid2, 256>>>(Cprev, nprev, out_C, out_h, out_n);
}